// round 4
// baseline (speedup 1.0000x reference)
#include <cuda_runtime.h>
#include <cuda_bf16.h>
#include <math.h>

// Problem shape (fixed by the reference)
#define B 32
#define S 4096
#define H 1024
#define CHUNKS 8                       // seq chunks per batch (split-softmax)
#define ROWS_PER_CTA (S / CHUNKS)      // 512
#define NWARPS 8
#define NTHREADS (NWARPS * 32)         // 256
#define ROWS_PER_WARP (ROWS_PER_CTA / NWARPS)  // 64

// Scratch for split-softmax partials (allocation-free: __device__ globals)
__device__ float g_ctx_partial[B][CHUNKS][H];  // exp-weighted (unnormalized) context per chunk
__device__ float g_m[B][CHUNKS];               // per-chunk running max
__device__ float g_l[B][CHUNKS];               // per-chunk running sum of exp

// ---------------------------------------------------------------------------
// Pass 1: single streaming read of encoder_outputs, software-pipelined.
// Decoder vector lives in SMEM (frees 32 regs); two register buffers (eA/eB)
// keep ~16 LDG.128 in flight per warp instead of 8.
// ---------------------------------------------------------------------------
__global__ void __launch_bounds__(NTHREADS, 2)
attn_pass1(const float* __restrict__ dec,   // [B, H]
           const float* __restrict__ enc,   // [B, S, H]
           float* __restrict__ attn_raw)    // [B, S] (raw scores for now)
{
    const int b    = blockIdx.y;
    const int c    = blockIdx.x;
    const int w    = threadIdx.x >> 5;
    const int lane = threadIdx.x & 31;

    __shared__ float4 sdec[H / 4];      // 4 KB
    __shared__ float  sm[NWARPS];
    __shared__ float  sl[NWARPS];
    __shared__ float  sctx[NWARPS][H];  // 32 KB

    // Cooperative load of decoder state into SMEM
    sdec[threadIdx.x] = ((const float4*)(dec + (size_t)b * H))[threadIdx.x];
    __syncthreads();

    float m = -INFINITY;
    float l = 0.0f;
    float4 ctx[8];
#pragma unroll
    for (int k = 0; k < 8; k++) ctx[k] = make_float4(0.f, 0.f, 0.f, 0.f);

    const int row0 = c * ROWS_PER_CTA + w * ROWS_PER_WARP;
    const float4* e4 = (const float4*)(enc + ((size_t)b * S + row0) * H);

    float4 eA[8], eB[8];

    // Prologue: load row 0 into eA
#pragma unroll
    for (int k = 0; k < 8; k++) eA[k] = __ldcs(e4 + lane + 32 * k);

    // Online-softmax update on a loaded row (d from SMEM, e in regs)
    auto process = [&](const float4* __restrict__ e, int s_local) {
        float acc = 0.f;
#pragma unroll
        for (int k = 0; k < 8; k++) {
            float4 dv = sdec[lane + 32 * k];
            acc = fmaf(dv.x, e[k].x, acc);
            acc = fmaf(dv.y, e[k].y, acc);
            acc = fmaf(dv.z, e[k].z, acc);
            acc = fmaf(dv.w, e[k].w, acc);
        }
#pragma unroll
        for (int off = 16; off; off >>= 1)
            acc += __shfl_xor_sync(0xffffffffu, acc, off);

        if (lane == 0) attn_raw[(size_t)b * S + row0 + s_local] = acc;

        const float mn    = fmaxf(m, acc);
        const float alpha = __expf(m - mn);
        const float wgt   = __expf(acc - mn);
        l = l * alpha + wgt;
#pragma unroll
        for (int k = 0; k < 8; k++) {
            ctx[k].x = ctx[k].x * alpha + wgt * e[k].x;
            ctx[k].y = ctx[k].y * alpha + wgt * e[k].y;
            ctx[k].z = ctx[k].z * alpha + wgt * e[k].z;
            ctx[k].w = ctx[k].w * alpha + wgt * e[k].w;
        }
        m = mn;
    };

    // Main loop: unroll-by-2 software pipeline.
    for (int r = 0; r < ROWS_PER_WARP; r += 2) {
        // eA holds row r; load row r+1 into eB, then compute on eA
        const float4* p1 = e4 + (size_t)(r + 1) * (H / 4);
#pragma unroll
        for (int k = 0; k < 8; k++) eB[k] = __ldcs(p1 + lane + 32 * k);

        process(eA, r);

        // Load row r+2 into eA (guarded), then compute on eB
        if (r + 2 < ROWS_PER_WARP) {
            const float4* p2 = e4 + (size_t)(r + 2) * (H / 4);
#pragma unroll
            for (int k = 0; k < 8; k++) eA[k] = __ldcs(p2 + lane + 32 * k);
        }

        process(eB, r + 1);
    }

    // ---- Merge 8 warps within the CTA ----
    if (lane == 0) { sm[w] = m; sl[w] = l; }
    __syncthreads();

    float M = -INFINITY;
#pragma unroll
    for (int w2 = 0; w2 < NWARPS; w2++) M = fmaxf(M, sm[w2]);
    float L = 0.f;
#pragma unroll
    for (int w2 = 0; w2 < NWARPS; w2++) L += sl[w2] * __expf(sm[w2] - M);

    const float scale = __expf(m - M);
    float4* my = (float4*)&sctx[w][0];
#pragma unroll
    for (int k = 0; k < 8; k++) {
        float4 v = ctx[k];
        v.x *= scale; v.y *= scale; v.z *= scale; v.w *= scale;
        my[lane + 32 * k] = v;
    }
    __syncthreads();

    const int t = threadIdx.x;
    float4 sum = make_float4(0.f, 0.f, 0.f, 0.f);
#pragma unroll
    for (int w2 = 0; w2 < NWARPS; w2++) {
        float4 v = ((float4*)&sctx[w2][0])[t];
        sum.x += v.x; sum.y += v.y; sum.z += v.z; sum.w += v.w;
    }
    ((float4*)&g_ctx_partial[b][c][0])[t] = sum;
    if (threadIdx.x == 0) { g_m[b][c] = M; g_l[b][c] = L; }
}

// ---------------------------------------------------------------------------
// Pass 2: grid (CHUNKS, B) = 256 CTAs. Every CTA redundantly recomputes the
// global (M, L) from the tiny partial arrays, then normalizes its own attn
// slice. The chunk-0 CTA additionally merges the context partials.
// ---------------------------------------------------------------------------
__global__ void __launch_bounds__(NTHREADS)
attn_pass2(float* __restrict__ out_ctx,   // [B, H]
           float* __restrict__ attn)      // [B, S] raw scores in, normalized out
{
    const int b = blockIdx.y;
    const int c = blockIdx.x;
    const int t = threadIdx.x;

    float M = -INFINITY;
#pragma unroll
    for (int k = 0; k < CHUNKS; k++) M = fmaxf(M, g_m[b][k]);
    float L = 0.f;
    float esc[CHUNKS];
#pragma unroll
    for (int k = 0; k < CHUNKS; k++) {
        esc[k] = __expf(g_m[b][k] - M);
        L += g_l[b][k] * esc[k];
    }
    const float invL = 1.0f / L;

    if (c == 0) {
        // Context merge: thread t owns float4 position t (256 float4 = 1024 floats)
        float4 s = make_float4(0.f, 0.f, 0.f, 0.f);
#pragma unroll
        for (int k = 0; k < CHUNKS; k++) {
            float4 v = ((const float4*)&g_ctx_partial[b][k][0])[t];
            s.x += v.x * esc[k]; s.y += v.y * esc[k];
            s.z += v.z * esc[k]; s.w += v.w * esc[k];
        }
        s.x *= invL; s.y *= invL; s.z *= invL; s.w *= invL;
        ((float4*)(out_ctx + (size_t)b * H))[t] = s;
    }

    // Normalize this chunk's attn slice: ROWS_PER_CTA=512 floats = 128 float4
    if (t < ROWS_PER_CTA / 4) {
        float4* a4 = (float4*)(attn + (size_t)b * S + (size_t)c * ROWS_PER_CTA);
        float4 v = a4[t];
        v.x = __expf(v.x - M) * invL;
        v.y = __expf(v.y - M) * invL;
        v.z = __expf(v.z - M) * invL;
        v.w = __expf(v.w - M) * invL;
        a4[t] = v;
    }
}

extern "C" void kernel_launch(void* const* d_in, const int* in_sizes, int n_in,
                              void* d_out, int out_size)
{
    const float* dec = (const float*)d_in[0];   // [B, H]
    const float* enc = (const float*)d_in[1];   // [B, S, H]
    float* out_ctx  = (float*)d_out;            // [B, H]
    float* out_attn = (float*)d_out + (size_t)B * H;  // [B, S]

    dim3 grid1(CHUNKS, B);
    attn_pass1<<<grid1, NTHREADS>>>(dec, enc, out_attn);
    dim3 grid2(CHUNKS, B);
    attn_pass2<<<grid2, NTHREADS>>>(out_ctx, out_attn);
}

// round 5
// speedup vs baseline: 1.1987x; 1.1987x over previous
#include <cuda_runtime.h>
#include <cuda_pipeline.h>
#include <math.h>

// Problem shape (fixed by the reference)
#define B 32
#define S 4096
#define H 1024
#define CHUNKS 8                        // seq chunks per batch (split-softmax)
#define ROWS_PER_CTA (S / CHUNKS)       // 512
#define NWARPS 8
#define NTHREADS 256
#define TILE_ROWS 16                    // rows per pipeline stage
#define NTILES (ROWS_PER_CTA / TILE_ROWS)   // 32
#define STAGES 3
#define TILE_FLOATS (TILE_ROWS * H)     // 16384 floats = 64 KB
#define SMEM_BYTES (STAGES * TILE_FLOATS * 4)  // 192 KB dynamic

// Scratch for split-softmax partials (allocation-free: __device__ globals)
__device__ float g_ctx_partial[B][CHUNKS][H];
__device__ float g_m[B][CHUNKS];
__device__ float g_l[B][CHUNKS];

// ---------------------------------------------------------------------------
// Pass 1: single streaming read of encoder_outputs via deep cp.async pipeline.
// 3-stage smem pipeline (64 KB tiles) keeps ~128 KB in flight per SM without
// consuming registers. Compute (dot + online softmax) reads from smem.
// ---------------------------------------------------------------------------
__global__ void __launch_bounds__(NTHREADS)
attn_pass1(const float* __restrict__ dec,   // [B, H]
           const float* __restrict__ enc,   // [B, S, H]
           float* __restrict__ attn_raw)    // [B, S] (raw scores for now)
{
    extern __shared__ float smem[];          // STAGES tile buffers
    __shared__ float sm[NWARPS];
    __shared__ float sl[NWARPS];

    const int b    = blockIdx.y;
    const int c    = blockIdx.x;
    const int t    = threadIdx.x;
    const int w    = t >> 5;
    const int lane = t & 31;

    // Decoder fragment in registers: lane owns float4 {lane, lane+32, ...}
    const float4* dec4 = (const float4*)(dec + (size_t)b * H);
    float4 d[8];
#pragma unroll
    for (int k = 0; k < 8; k++) d[k] = __ldg(dec4 + lane + 32 * k);

    const int row0 = c * ROWS_PER_CTA;
    const float* src_base = enc + ((size_t)b * S + row0) * H;

    // Issue async copy of tile i into buffer i%STAGES (64 KB contiguous).
    // 256 threads x 16 float4 each.
    auto issue_tile = [&](int i) {
        const float4* src = (const float4*)(src_base + (size_t)i * TILE_FLOATS);
        float4* dst = (float4*)(smem + (size_t)(i % STAGES) * TILE_FLOATS);
#pragma unroll
        for (int j = 0; j < TILE_FLOATS / 4 / NTHREADS; j++)   // 16
            __pipeline_memcpy_async(dst + t + NTHREADS * j,
                                    src + t + NTHREADS * j, 16);
    };

    // Prologue: stages 0..STAGES-2 in flight
#pragma unroll
    for (int s = 0; s < STAGES - 1; s++) { issue_tile(s); __pipeline_commit(); }

    float m = -INFINITY;
    float l = 0.0f;
    float4 ctx[8];
#pragma unroll
    for (int k = 0; k < 8; k++) ctx[k] = make_float4(0.f, 0.f, 0.f, 0.f);

    for (int i = 0; i < NTILES; i++) {
        // Keep the pipeline full: issue tile i+STAGES-1 (buffer freed at i-1)
        if (i + STAGES - 1 < NTILES) issue_tile(i + STAGES - 1);
        __pipeline_commit();
        __pipeline_wait_prior(STAGES - 1);   // tile i's copy complete (this thread)
        __syncthreads();                     // visible to all warps

        const float* buf = smem + (size_t)(i % STAGES) * TILE_FLOATS;

        // Warp w computes tile-local rows {w, w+8}
#pragma unroll
        for (int rr = 0; rr < TILE_ROWS / NWARPS; rr++) {
            const int row = w + rr * NWARPS;
            const float4* e4 = (const float4*)(buf + (size_t)row * H);

            float4 e[8];
#pragma unroll
            for (int k = 0; k < 8; k++) e[k] = e4[lane + 32 * k];

            float acc = 0.f;
#pragma unroll
            for (int k = 0; k < 8; k++) {
                acc = fmaf(d[k].x, e[k].x, acc);
                acc = fmaf(d[k].y, e[k].y, acc);
                acc = fmaf(d[k].z, e[k].z, acc);
                acc = fmaf(d[k].w, e[k].w, acc);
            }
#pragma unroll
            for (int off = 16; off; off >>= 1)
                acc += __shfl_xor_sync(0xffffffffu, acc, off);

            if (lane == 0)
                attn_raw[(size_t)b * S + row0 + i * TILE_ROWS + row] = acc;

            // Online softmax update
            const float mn    = fmaxf(m, acc);
            const float alpha = __expf(m - mn);     // exp(-inf)=0 on first row
            const float wgt   = __expf(acc - mn);
            l = l * alpha + wgt;
#pragma unroll
            for (int k = 0; k < 8; k++) {
                ctx[k].x = ctx[k].x * alpha + wgt * e[k].x;
                ctx[k].y = ctx[k].y * alpha + wgt * e[k].y;
                ctx[k].z = ctx[k].z * alpha + wgt * e[k].z;
                ctx[k].w = ctx[k].w * alpha + wgt * e[k].w;
            }
            m = mn;
        }
        __syncthreads();   // all warps done reading before buffer reuse
    }

    // ---- Merge 8 warps within the CTA (reuse smem for staging) ----
    if (lane == 0) { sm[w] = m; sl[w] = l; }
    __syncthreads();

    float M = -INFINITY;
#pragma unroll
    for (int w2 = 0; w2 < NWARPS; w2++) M = fmaxf(M, sm[w2]);
    float L = 0.f;
#pragma unroll
    for (int w2 = 0; w2 < NWARPS; w2++) L += sl[w2] * __expf(sm[w2] - M);

    float* sctx = smem;   // 8 x 1024 floats = 32 KB, aliases stage buffer 0
    const float scale = __expf(m - M);
    float4* my = (float4*)(sctx + (size_t)w * H);
#pragma unroll
    for (int k = 0; k < 8; k++) {
        float4 v = ctx[k];
        v.x *= scale; v.y *= scale; v.z *= scale; v.w *= scale;
        my[lane + 32 * k] = v;
    }
    __syncthreads();

    float4 sum = make_float4(0.f, 0.f, 0.f, 0.f);
#pragma unroll
    for (int w2 = 0; w2 < NWARPS; w2++) {
        float4 v = ((float4*)(sctx + (size_t)w2 * H))[t];
        sum.x += v.x; sum.y += v.y; sum.z += v.z; sum.w += v.w;
    }
    ((float4*)&g_ctx_partial[b][c][0])[t] = sum;
    if (t == 0) { g_m[b][c] = M; g_l[b][c] = L; }
}

// ---------------------------------------------------------------------------
// Pass 2: grid (CHUNKS, B). Attn-slice load is issued BEFORE the dependent
// (M, L) computation so the two DRAM latencies overlap. Chunk-0 CTA also
// merges the context partials.
// ---------------------------------------------------------------------------
__global__ void __launch_bounds__(NTHREADS)
attn_pass2(float* __restrict__ out_ctx,   // [B, H]
           float* __restrict__ attn)      // [B, S] raw scores in, normalized out
{
    const int b = blockIdx.y;
    const int c = blockIdx.x;
    const int t = threadIdx.x;

    // Independent prefetch of this CTA's attn slice (512 floats = 128 float4)
    float4* a4 = (float4*)(attn + (size_t)b * S + (size_t)c * ROWS_PER_CTA);
    float4 v;
    const bool has = t < ROWS_PER_CTA / 4;
    if (has) v = a4[t];

    // Global max / sum from the tiny partial arrays (L2-hot after first CTA)
    float M = -INFINITY;
#pragma unroll
    for (int k = 0; k < CHUNKS; k++) M = fmaxf(M, __ldg(&g_m[b][k]));
    float L = 0.f;
    float esc[CHUNKS];
#pragma unroll
    for (int k = 0; k < CHUNKS; k++) {
        esc[k] = __expf(__ldg(&g_m[b][k]) - M);
        L += __ldg(&g_l[b][k]) * esc[k];
    }
    const float invL = 1.0f / L;

    if (c == 0) {
        // Context merge: thread t owns float4 position t (256 float4 = 1024 f)
        float4 s = make_float4(0.f, 0.f, 0.f, 0.f);
#pragma unroll
        for (int k = 0; k < CHUNKS; k++) {
            float4 p = ((const float4*)&g_ctx_partial[b][k][0])[t];
            s.x += p.x * esc[k]; s.y += p.y * esc[k];
            s.z += p.z * esc[k]; s.w += p.w * esc[k];
        }
        s.x *= invL; s.y *= invL; s.z *= invL; s.w *= invL;
        ((float4*)(out_ctx + (size_t)b * H))[t] = s;
    }

    if (has) {
        v.x = __expf(v.x - M) * invL;
        v.y = __expf(v.y - M) * invL;
        v.z = __expf(v.z - M) * invL;
        v.w = __expf(v.w - M) * invL;
        a4[t] = v;
    }
}

extern "C" void kernel_launch(void* const* d_in, const int* in_sizes, int n_in,
                              void* d_out, int out_size)
{
    const float* dec = (const float*)d_in[0];   // [B, H]
    const float* enc = (const float*)d_in[1];   // [B, S, H]
    float* out_ctx  = (float*)d_out;            // [B, H]
    float* out_attn = (float*)d_out + (size_t)B * H;  // [B, S]

    // Opt in to >48 KB dynamic smem (host attribute set; not a stream op,
    // graph-capture safe; idempotent).
    cudaFuncSetAttribute(attn_pass1,
                         cudaFuncAttributeMaxDynamicSharedMemorySize,
                         SMEM_BYTES);

    dim3 grid1(CHUNKS, B);
    attn_pass1<<<grid1, NTHREADS, SMEM_BYTES>>>(dec, enc, out_attn);
    dim3 grid2(CHUNKS, B);
    attn_pass2<<<grid2, NTHREADS>>>(out_ctx, out_attn);
}

// round 6
// speedup vs baseline: 1.2740x; 1.0629x over previous
#include <cuda_runtime.h>
#include <cuda_pipeline.h>
#include <math.h>

// Problem shape (fixed by the reference)
#define B 32
#define S 4096
#define H 1024
#define CHUNKS 4                        // seq chunks per batch -> grid 128 = ONE wave
#define ROWS_PER_CTA (S / CHUNKS)       // 1024
#define NWARPS 8
#define NTHREADS 256
#define TILE_ROWS 16                    // rows per pipeline stage
#define NTILES (ROWS_PER_CTA / TILE_ROWS)   // 64
#define STAGES 3
#define TILE_FLOATS (TILE_ROWS * H)     // 16384 floats = 64 KB
#define SMEM_BYTES (STAGES * TILE_FLOATS * 4)  // 192 KB dynamic

// Scratch for split-softmax partials (allocation-free: __device__ globals)
__device__ float g_ctx_partial[B][CHUNKS][H];
__device__ float g_m[B][CHUNKS];
__device__ float g_l[B][CHUNKS];

// ---------------------------------------------------------------------------
// Pass 1: single streaming read of encoder_outputs via deep cp.async pipeline.
// Grid (CHUNKS=4, B=32) = 128 CTAs -> single wave at occupancy 1.
// 3-stage smem pipeline (64 KB tiles) keeps 128 KB in flight per SM without
// consuming registers. Compute (dot + online softmax) reads from smem.
// ---------------------------------------------------------------------------
__global__ void __launch_bounds__(NTHREADS)
attn_pass1(const float* __restrict__ dec,   // [B, H]
           const float* __restrict__ enc,   // [B, S, H]
           float* __restrict__ attn_raw)    // [B, S] (raw scores for now)
{
    extern __shared__ float smem[];          // STAGES tile buffers
    __shared__ float sm[NWARPS];
    __shared__ float sl[NWARPS];

    const int b    = blockIdx.y;
    const int c    = blockIdx.x;
    const int t    = threadIdx.x;
    const int w    = t >> 5;
    const int lane = t & 31;

    // Decoder fragment in registers: lane owns float4 {lane, lane+32, ...}
    const float4* dec4 = (const float4*)(dec + (size_t)b * H);
    float4 d[8];
#pragma unroll
    for (int k = 0; k < 8; k++) d[k] = __ldg(dec4 + lane + 32 * k);

    const int row0 = c * ROWS_PER_CTA;
    const float* src_base = enc + ((size_t)b * S + row0) * H;

    // Issue async copy of tile i into buffer i%STAGES (64 KB contiguous).
    // 256 threads x 16 float4 each.
    auto issue_tile = [&](int i) {
        const float4* src = (const float4*)(src_base + (size_t)i * TILE_FLOATS);
        float4* dst = (float4*)(smem + (size_t)(i % STAGES) * TILE_FLOATS);
#pragma unroll
        for (int j = 0; j < TILE_FLOATS / 4 / NTHREADS; j++)   // 16
            __pipeline_memcpy_async(dst + t + NTHREADS * j,
                                    src + t + NTHREADS * j, 16);
    };

    // Prologue: stages 0..STAGES-2 in flight
#pragma unroll
    for (int s = 0; s < STAGES - 1; s++) { issue_tile(s); __pipeline_commit(); }

    float m = -INFINITY;
    float l = 0.0f;
    float4 ctx[8];
#pragma unroll
    for (int k = 0; k < 8; k++) ctx[k] = make_float4(0.f, 0.f, 0.f, 0.f);

    for (int i = 0; i < NTILES; i++) {
        // Keep the pipeline full (buffer (i-1)%STAGES was freed by the
        // trailing __syncthreads of iteration i-1)
        if (i + STAGES - 1 < NTILES) issue_tile(i + STAGES - 1);
        __pipeline_commit();
        __pipeline_wait_prior(STAGES - 1);   // tile i's copy complete (this thread)
        __syncthreads();                     // visible to all warps

        const float* buf = smem + (size_t)(i % STAGES) * TILE_FLOATS;

        // Warp w computes tile-local rows {w, w+8}
#pragma unroll
        for (int rr = 0; rr < TILE_ROWS / NWARPS; rr++) {
            const int row = w + rr * NWARPS;
            const float4* e4 = (const float4*)(buf + (size_t)row * H);

            float4 e[8];
#pragma unroll
            for (int k = 0; k < 8; k++) e[k] = e4[lane + 32 * k];

            float acc = 0.f;
#pragma unroll
            for (int k = 0; k < 8; k++) {
                acc = fmaf(d[k].x, e[k].x, acc);
                acc = fmaf(d[k].y, e[k].y, acc);
                acc = fmaf(d[k].z, e[k].z, acc);
                acc = fmaf(d[k].w, e[k].w, acc);
            }
#pragma unroll
            for (int off = 16; off; off >>= 1)
                acc += __shfl_xor_sync(0xffffffffu, acc, off);

            if (lane == 0)
                attn_raw[(size_t)b * S + row0 + i * TILE_ROWS + row] = acc;

            // Online softmax update
            const float mn    = fmaxf(m, acc);
            const float alpha = __expf(m - mn);     // exp(-inf)=0 on first row
            const float wgt   = __expf(acc - mn);
            l = l * alpha + wgt;
#pragma unroll
            for (int k = 0; k < 8; k++) {
                ctx[k].x = ctx[k].x * alpha + wgt * e[k].x;
                ctx[k].y = ctx[k].y * alpha + wgt * e[k].y;
                ctx[k].z = ctx[k].z * alpha + wgt * e[k].z;
                ctx[k].w = ctx[k].w * alpha + wgt * e[k].w;
            }
            m = mn;
        }
        __syncthreads();   // all warps done reading before buffer reuse
    }

    // ---- Merge 8 warps within the CTA (reuse stage buffer 0 for staging) ----
    if (lane == 0) { sm[w] = m; sl[w] = l; }
    __syncthreads();

    float M = -INFINITY;
#pragma unroll
    for (int w2 = 0; w2 < NWARPS; w2++) M = fmaxf(M, sm[w2]);
    float L = 0.f;
#pragma unroll
    for (int w2 = 0; w2 < NWARPS; w2++) L += sl[w2] * __expf(sm[w2] - M);

    float* sctx = smem;   // 8 x 1024 floats = 32 KB, aliases stage buffer 0
    const float scale = __expf(m - M);
    float4* my = (float4*)(sctx + (size_t)w * H);
#pragma unroll
    for (int k = 0; k < 8; k++) {
        float4 v = ctx[k];
        v.x *= scale; v.y *= scale; v.z *= scale; v.w *= scale;
        my[lane + 32 * k] = v;
    }
    __syncthreads();

    float4 sum = make_float4(0.f, 0.f, 0.f, 0.f);
#pragma unroll
    for (int w2 = 0; w2 < NWARPS; w2++) {
        float4 v = ((float4*)(sctx + (size_t)w2 * H))[t];
        sum.x += v.x; sum.y += v.y; sum.z += v.z; sum.w += v.w;
    }
    ((float4*)&g_ctx_partial[b][c][0])[t] = sum;
    if (t == 0) { g_m[b][c] = M; g_l[b][c] = L; }
}

// ---------------------------------------------------------------------------
// Pass 2: grid (CHUNKS, B) = 128 CTAs. Attn-slice load issued BEFORE the
// dependent (M, L) computation so the DRAM latencies overlap. Chunk-0 CTA
// also merges the context partials. Slice = 1024 floats = 256 float4 = one
// per thread.
// ---------------------------------------------------------------------------
__global__ void __launch_bounds__(NTHREADS)
attn_pass2(float* __restrict__ out_ctx,   // [B, H]
           float* __restrict__ attn)      // [B, S] raw scores in, normalized out
{
    const int b = blockIdx.y;
    const int c = blockIdx.x;
    const int t = threadIdx.x;

    // Independent prefetch of this CTA's attn slice
    float4* a4 = (float4*)(attn + (size_t)b * S + (size_t)c * ROWS_PER_CTA);
    float4 v = a4[t];

    // Global max / sum from the tiny partial arrays (L2-hot after first CTA)
    float M = -INFINITY;
#pragma unroll
    for (int k = 0; k < CHUNKS; k++) M = fmaxf(M, __ldg(&g_m[b][k]));
    float L = 0.f;
    float esc[CHUNKS];
#pragma unroll
    for (int k = 0; k < CHUNKS; k++) {
        esc[k] = __expf(__ldg(&g_m[b][k]) - M);
        L += __ldg(&g_l[b][k]) * esc[k];
    }
    const float invL = 1.0f / L;

    if (c == 0) {
        // Context merge: thread t owns float4 position t (256 float4 = 1024 f)
        float4 s = make_float4(0.f, 0.f, 0.f, 0.f);
#pragma unroll
        for (int k = 0; k < CHUNKS; k++) {
            float4 p = ((const float4*)&g_ctx_partial[b][k][0])[t];
            s.x += p.x * esc[k]; s.y += p.y * esc[k];
            s.z += p.z * esc[k]; s.w += p.w * esc[k];
        }
        s.x *= invL; s.y *= invL; s.z *= invL; s.w *= invL;
        ((float4*)(out_ctx + (size_t)b * H))[t] = s;
    }

    v.x = __expf(v.x - M) * invL;
    v.y = __expf(v.y - M) * invL;
    v.z = __expf(v.z - M) * invL;
    v.w = __expf(v.w - M) * invL;
    a4[t] = v;
}

extern "C" void kernel_launch(void* const* d_in, const int* in_sizes, int n_in,
                              void* d_out, int out_size)
{
    const float* dec = (const float*)d_in[0];   // [B, H]
    const float* enc = (const float*)d_in[1];   // [B, S, H]
    float* out_ctx  = (float*)d_out;            // [B, H]
    float* out_attn = (float*)d_out + (size_t)B * H;  // [B, S]

    // Opt in to >48 KB dynamic smem (host attribute; graph-capture safe).
    cudaFuncSetAttribute(attn_pass1,
                         cudaFuncAttributeMaxDynamicSharedMemorySize,
                         SMEM_BYTES);

    dim3 grid1(CHUNKS, B);
    attn_pass1<<<grid1, NTHREADS, SMEM_BYTES>>>(dec, enc, out_attn);
    dim3 grid2(CHUNKS, B);
    attn_pass2<<<grid2, NTHREADS>>>(out_ctx, out_attn);
}